// round 12
// baseline (speedup 1.0000x reference)
#include <cuda_runtime.h>
#include <math.h>

// ---------------- fixed problem shapes ----------------
#define NN   4
#define CC   1024
#define DD   768
#define HH   12
#define EE   32
#define MM   4
#define PP   256
#define RR   (NN*PP)     // 1024
#define KBL  12
#define NOUT 97

#define WSCALE     1024.0f
#define WSCALE_INV (1.0f/1024.0f)

// ---------------- scratch ----------------
__device__ float g_ent_emb[NN*EE*DD];
__device__ float g_ent_att[NN*EE*HH*CC];
__device__ float g_ht_att [NN*PP*CC];
__device__ float g_rs     [RR*DD];
__device__ float g_hs2    [RR*DD];
__device__ float g_ts2    [RR*DD];

// W_bil fragments (fp16, x1024): 3072 chunks x 13 nt x 32 lanes x uint2
__device__ __align__(16) unsigned char g_Wp[3072UL*13*32*8];
// W_head/W_tail fragments (fp16, x1024): [2][96 kc][96 nt][32] uint2
__device__ __align__(16) unsigned char g_Whtp[2UL*96*96*32*8];
// seq fragments (fp16, unscaled): [4][64 kc][96 nt][32] uint2
__device__ __align__(16) unsigned char g_seqf[4UL*64*96*32*8];

// ---------------- fp16 helpers ----------------
__device__ __forceinline__ unsigned pack_f16x2(float hi_f, float lo_f) {
    unsigned r;
    asm("cvt.rn.f16x2.f32 %0, %1, %2;" : "=r"(r) : "f"(hi_f), "f"(lo_f));
    return r;
}
// split (p0 lower, p1 upper) into f16x2 hi + f16x2 lo residual (~22-bit total)
__device__ __forceinline__ void split2h(float p0, float p1, unsigned& hi, unsigned& lo) {
    hi = pack_f16x2(p1, p0);
    float f0, f1;
    asm("{\n\t.reg .b16 h0, h1;\n\t"
        "mov.b32 {h0, h1}, %2;\n\t"
        "cvt.f32.f16 %0, h0;\n\t"
        "cvt.f32.f16 %1, h1;\n\t}"
        : "=f"(f0), "=f"(f1) : "r"(hi));
    lo = pack_f16x2(p1 - f1, p0 - f0);
}
// warp mma: D += A(f16) * B(f16), m16n8k16, row.col, fp32 accum
__device__ __forceinline__ void mma_f16(float* d, const unsigned* a,
                                        unsigned b0, unsigned b1) {
    asm volatile(
        "mma.sync.aligned.m16n8k16.row.col.f32.f16.f16.f32 "
        "{%0,%1,%2,%3}, {%4,%5,%6,%7}, {%8,%9}, {%0,%1,%2,%3};"
        : "+f"(d[0]), "+f"(d[1]), "+f"(d[2]), "+f"(d[3])
        : "r"(a[0]), "r"(a[1]), "r"(a[2]), "r"(a[3]), "r"(b0), "r"(b1));
}

// stage one float4 (pairs p0=2*quad, p0+1) into packed fragment row.
// slot(q) = q<4 ? 4q : 4(q-4)+1 ; hi at slot, lo at slot+2.
__device__ __forceinline__ void stage_pairs(unsigned* dst_row, int quad, float4 v) {
    unsigned hi0, lo0, hi1, lo1;
    split2h(v.x, v.y, hi0, lo0);
    split2h(v.z, v.w, hi1, lo1);
    int p0 = quad*2, p1 = p0 + 1;
    int s0 = (p0 < 4) ? 4*p0 : 4*(p0 - 4) + 1;
    int s1 = (p1 < 4) ? 4*p1 : 4*(p1 - 4) + 1;
    dst_row[s0] = hi0; dst_row[s0 + 2] = lo0;
    dst_row[s1] = hi1; dst_row[s1 + 2] = lo1;
}

// ============================================================================
// P0: pack W_bil (x1024, fp16) into B-fragment layout. grid 3072, 128 thr
// ============================================================================
__global__ void k_wt(const float* __restrict__ Wb) {
    __shared__ float Wsm[16*104];
    int chunk = blockIdx.x;
    int tid = threadIdx.x;
    int row0 = chunk * 16;

    for (int idx = tid; idx < 16*104; idx += 128) {
        int r = idx / 104, n = idx - r*104;
        Wsm[idx] = (n < NOUT) ? Wb[(size_t)(row0 + r)*NOUT + n] * WSCALE : 0.0f;
    }
    __syncthreads();

    for (int e = tid; e < 13*32; e += 128) {
        int nt = e >> 5, lane = e & 31;
        int g = lane >> 2, t = lane & 3;
        int n = nt*8 + g, k0 = 2*t;
        unsigned b0 = pack_f16x2(Wsm[(k0 + 1)*104 + n], Wsm[(k0    )*104 + n]);
        unsigned b1 = pack_f16x2(Wsm[(k0 + 9)*104 + n], Wsm[(k0 + 8)*104 + n]);
        *(uint2*)(g_Wp + ((size_t)(chunk*13 + nt)*32 + lane)*8) = make_uint2(b0, b1);
    }
}

// ============================================================================
// P1: pack W_head / W_tail (x1024, fp16). grid (96, 2), 256 thr
// ============================================================================
__global__ void k_wht(const float* __restrict__ Wh, const float* __restrict__ Wt) {
    __shared__ float S[16*768];
    int kc = blockIdx.x;
    int w  = blockIdx.y;
    const float* W = w ? Wt : Wh;
    int tid = threadIdx.x;

    for (int idx = tid; idx < 16*768; idx += 256)
        S[idx] = W[(size_t)kc*16*768 + idx] * WSCALE;
    __syncthreads();

    for (int e = tid; e < 96*32; e += 256) {
        int nt = e >> 5, lane = e & 31;
        int g = lane >> 2, t = lane & 3;
        int n = nt*8 + g, k0 = 2*t;
        unsigned b0 = pack_f16x2(S[(k0 + 1)*768 + n], S[(k0    )*768 + n]);
        unsigned b1 = pack_f16x2(S[(k0 + 9)*768 + n], S[(k0 + 8)*768 + n]);
        *(uint2*)(g_Whtp + ((((size_t)w*96 + kc)*96 + nt)*32 + lane)*8) = make_uint2(b0, b1);
    }
}

// ============================================================================
// P2: pack seq (fp16, unscaled). grid (64, 4), 256 thr
// ============================================================================
__global__ void k_seqf(const float* __restrict__ seq) {
    __shared__ float S[16*768];
    int kc = blockIdx.x;
    int b  = blockIdx.y;
    int tid = threadIdx.x;

    for (int idx = tid; idx < 16*768; idx += 256)
        S[idx] = seq[((size_t)b*CC + kc*16)*768 + idx];
    __syncthreads();

    for (int e = tid; e < 96*32; e += 256) {
        int nt = e >> 5, lane = e & 31;
        int g = lane >> 2, t = lane & 3;
        int n = nt*8 + g, k0 = 2*t;
        unsigned b0 = pack_f16x2(S[(k0 + 1)*768 + n], S[(k0    )*768 + n]);
        unsigned b1 = pack_f16x2(S[(k0 + 9)*768 + n], S[(k0 + 8)*768 + n]);
        *(uint2*)(g_seqf + ((((size_t)b*64 + kc)*96 + nt)*32 + lane)*8) = make_uint2(b0, b1);
    }
}

// ============================================================================
// K1: entity embeddings = logsumexp over M mentions. grid (128, 2)
// ============================================================================
__global__ void k_ent_emb(const float* __restrict__ seq,
                          const int*   __restrict__ mpos) {
    int be = blockIdx.x;
    int half = blockIdx.y;
    int b  = be / EE;
    const int* mp = mpos + be*MM;
    int p0 = mp[0], p1 = mp[1], p2 = mp[2], p3 = mp[3];
    const float* sb = seq + (long)b*CC*DD;
    int d0 = half*(DD/2), d1 = d0 + DD/2;
    for (int dd = d0 + threadIdx.x; dd < d1; dd += blockDim.x) {
        float v0 = sb[p0*DD+dd], v1 = sb[p1*DD+dd];
        float v2 = sb[p2*DD+dd], v3 = sb[p3*DD+dd];
        float mx = fmaxf(fmaxf(v0, v1), fmaxf(v2, v3));
        float s  = expf(v0-mx) + expf(v1-mx) + expf(v2-mx) + expf(v3-mx);
        g_ent_emb[be*DD + dd] = mx + logf(s);
    }
}

// ============================================================================
// K2: entity attention = mean over M mention attention rows
// ============================================================================
__global__ void k_ent_att(const float* __restrict__ att,
                          const int*   __restrict__ mpos) {
    int id = blockIdx.x;
    int hd = id % HH;
    int be = id / HH;
    int b  = be / EE;
    const int* mp = mpos + be*MM;
    const float* ab = att + (long)(b*HH + hd)*CC*CC;
    float* ob = g_ent_att + (long)id*CC;
    int q0 = mp[0]*CC, q1 = mp[1]*CC, q2 = mp[2]*CC, q3 = mp[3]*CC;
    for (int c = threadIdx.x; c < CC; c += blockDim.x) {
        float s = ab[q0+c] + ab[q1+c] + ab[q2+c] + ab[q3+c];
        ob[c] = s * 0.25f;
    }
}

// ============================================================================
// K3: ht_att = mean_h(h_att * t_att), row-normalized
// ============================================================================
__global__ void k_ht_att(const int* __restrict__ hts) {
    int bp = blockIdx.x;
    int b  = bp / PP;
    int eh = hts[bp*2 + 0];
    int et = hts[bp*2 + 1];
    const float* ah = g_ent_att + (long)(b*EE + eh)*HH*CC;
    const float* at = g_ent_att + (long)(b*EE + et)*HH*CC;

    float v[4];
    float lsum = 0.f;
    #pragma unroll
    for (int q = 0; q < 4; q++) {
        int c = q*256 + threadIdx.x;
        float s = 0.f;
        #pragma unroll
        for (int hd = 0; hd < HH; hd++)
            s += ah[hd*CC + c] * at[hd*CC + c];
        s *= (1.0f / HH);
        v[q] = s;
        lsum += s;
    }
    __shared__ float red[256];
    red[threadIdx.x] = lsum;
    __syncthreads();
    for (int st = 128; st > 0; st >>= 1) {
        if (threadIdx.x < st) red[threadIdx.x] += red[threadIdx.x + st];
        __syncthreads();
    }
    float inv = 1.0f / (red[0] + 1e-30f);
    #pragma unroll
    for (int q = 0; q < 4; q++) {
        int c = q*256 + threadIdx.x;
        g_ht_att[(long)bp*CC + c] = v[q] * inv;
    }
}

// ============================================================================
// K4: rs = ht_att @ seq, fp16 2-term mma, DEPTH-2 pipeline (3-buf A, 2-deep B).
// grid (12, 32) = 384 CTAs, 128 thr.
// ============================================================================
#define APITCH 20
__global__ void __launch_bounds__(128) k_rs_mma() {
    __shared__ __align__(16) unsigned As[3][32*APITCH];

    int ntg0 = blockIdx.x * 8;
    int r0   = blockIdx.y * 32;
    int b    = r0 >> 8;
    int tid = threadIdx.x, wid = tid >> 5, lane = tid & 31;
    int g = lane >> 2, t = lane & 3;

    int arow = tid >> 2;
    int quad = tid & 3;
    const float* Arow = g_ht_att + (size_t)(r0 + arow)*CC + quad*4;

    const char* Bp0 = (const char*)g_seqf + (((size_t)b*64*96) + ntg0 + wid*2    )*256 + lane*8;
    const char* Bp1 = (const char*)g_seqf + (((size_t)b*64*96) + ntg0 + wid*2 + 1)*256 + lane*8;
    const size_t KSTR = (size_t)96*256;

    // prologue: stage A(0); hold B(0); prefetch A(1), B(1)
    float4 pa0 = *(const float4*)(Arow);
    pa0.x *= WSCALE; pa0.y *= WSCALE; pa0.z *= WSCALE; pa0.w *= WSCALE;
    stage_pairs(&As[0][arow*APITCH], quad, pa0);
    uint2 bc0 = *(const uint2*)(Bp0);
    uint2 bc1 = *(const uint2*)(Bp1);
    float4 pa1 = *(const float4*)(Arow + 16);
    pa1.x *= WSCALE; pa1.y *= WSCALE; pa1.z *= WSCALE; pa1.w *= WSCALE;
    uint2 nb0 = *(const uint2*)(Bp0 + KSTR);
    uint2 nb1 = *(const uint2*)(Bp1 + KSTR);
    __syncthreads();

    unsigned* Acur = &As[0][0];
    unsigned* Anxt = &As[1][0];
    unsigned* Afree = &As[2][0];

    float acc[2][2][4];
    #pragma unroll
    for (int a = 0; a < 2; a++)
        #pragma unroll
        for (int n = 0; n < 2; n++)
            #pragma unroll
            for (int c = 0; c < 4; c++) acc[a][n][c] = 0.0f;

    for (int ks = 0; ks < 64; ks++) {
        float4 pa2;
        uint2 fb0, fb1;
        if (ks + 2 < 64) {
            pa2 = *(const float4*)(Arow + (ks + 2)*16);
            pa2.x *= WSCALE; pa2.y *= WSCALE; pa2.z *= WSCALE; pa2.w *= WSCALE;
            fb0 = *(const uint2*)(Bp0 + (size_t)(ks + 2)*KSTR);
            fb1 = *(const uint2*)(Bp1 + (size_t)(ks + 2)*KSTR);
        }
        if (ks + 1 < 64)
            stage_pairs(&Anxt[arow*APITCH], quad, pa1);

        #pragma unroll
        for (int af = 0; af < 2; af++) {
            int ra = af*16 + g, rb = ra + 8;
            uint4 ua = *(const uint4*)&Acur[ra*APITCH + 4*t];
            uint4 ub = *(const uint4*)&Acur[rb*APITCH + 4*t];
            unsigned ahi[4] = {ua.x, ub.x, ua.y, ub.y};
            unsigned alo[4] = {ua.z, ub.z, ua.w, ub.w};
            mma_f16(acc[af][0], ahi, bc0.x, bc0.y);
            mma_f16(acc[af][0], alo, bc0.x, bc0.y);
            mma_f16(acc[af][1], ahi, bc1.x, bc1.y);
            mma_f16(acc[af][1], alo, bc1.x, bc1.y);
        }

        bc0 = nb0; bc1 = nb1;
        nb0 = fb0; nb1 = fb1;
        pa1 = pa2;
        unsigned* tmp = Acur; Acur = Anxt; Anxt = Afree; Afree = tmp;
        __syncthreads();
    }

    #pragma unroll
    for (int af = 0; af < 2; af++) {
        int ra = r0 + af*16 + g;
        #pragma unroll
        for (int nt = 0; nt < 2; nt++) {
            int n0 = (ntg0 + wid*2 + nt)*8 + 2*t;
            *(float2*)(g_rs + (size_t)ra*DD + n0) =
                make_float2(acc[af][nt][0]*WSCALE_INV, acc[af][nt][1]*WSCALE_INV);
            *(float2*)(g_rs + (size_t)(ra+8)*DD + n0) =
                make_float2(acc[af][nt][2]*WSCALE_INV, acc[af][nt][3]*WSCALE_INV);
        }
    }
}

// ============================================================================
// K5: hs2/ts2 = tanh(concat(ent_emb[ent], rs) @ W + b), DEPTH-2 pipeline.
// grid (12, 32, 2).
// ============================================================================
__global__ void __launch_bounds__(128) k_ht_mma(const float* __restrict__ bh,
                                                const float* __restrict__ bt,
                                                const int* __restrict__ hts) {
    __shared__ __align__(16) unsigned As[3][32*APITCH];
    __shared__ int eOff[32];

    int ntg0 = blockIdx.x * 8;
    int r0   = blockIdx.y * 32;
    int col  = blockIdx.z;
    const float* bias = col ? bt : bh;
    float* outm = col ? g_ts2 : g_hs2;

    int tid = threadIdx.x, wid = tid >> 5, lane = tid & 31;
    int g = lane >> 2, t = lane & 3;

    if (tid < 32) {
        int r = r0 + tid;
        eOff[tid] = ((r >> 8)*EE + hts[r*2 + col])*DD;
    }
    __syncthreads();

    int arow = tid >> 2;
    int quad = tid & 3;
    const float* rRow = g_rs + (size_t)(r0 + arow)*DD + quad*4;
    int eBase = eOff[arow] + quad*4;

    const char* Bp0 = (const char*)g_Whtp + (((size_t)col*96*96) + ntg0 + wid*2    )*256 + lane*8;
    const char* Bp1 = (const char*)g_Whtp + (((size_t)col*96*96) + ntg0 + wid*2 + 1)*256 + lane*8;
    const size_t KSTR = (size_t)96*256;

    // prologue
    float4 pa0 = *(const float4*)(g_ent_emb + eBase);
    stage_pairs(&As[0][arow*APITCH], quad, pa0);
    uint2 bc0 = *(const uint2*)(Bp0);
    uint2 bc1 = *(const uint2*)(Bp1);
    float4 pa1 = *(const float4*)(g_ent_emb + eBase + 16);
    uint2 nb0 = *(const uint2*)(Bp0 + KSTR);
    uint2 nb1 = *(const uint2*)(Bp1 + KSTR);
    __syncthreads();

    unsigned* Acur = &As[0][0];
    unsigned* Anxt = &As[1][0];
    unsigned* Afree = &As[2][0];

    float acc[2][2][4];
    #pragma unroll
    for (int a = 0; a < 2; a++)
        #pragma unroll
        for (int n = 0; n < 2; n++)
            #pragma unroll
            for (int c = 0; c < 4; c++) acc[a][n][c] = 0.0f;

    const int NK = 96;
    for (int ks = 0; ks < NK; ks++) {
        float4 pa2;
        uint2 fb0, fb1;
        if (ks + 2 < NK) {
            int kc = (ks + 2)*16;
            pa2 = (kc < DD) ? *(const float4*)(g_ent_emb + eBase + kc)
                            : *(const float4*)(rRow + kc - DD);
            fb0 = *(const uint2*)(Bp0 + (size_t)(ks + 2)*KSTR);
            fb1 = *(const uint2*)(Bp1 + (size_t)(ks + 2)*KSTR);
        }
        if (ks + 1 < NK)
            stage_pairs(&Anxt[arow*APITCH], quad, pa1);

        #pragma unroll
        for (int af = 0; af < 2; af++) {
            int ra = af*16 + g, rb = ra + 8;
            uint4 ua = *(const uint4*)&Acur[ra*APITCH + 4*t];
            uint4 ub = *(const uint4*)&Acur[rb*APITCH + 4*t];
            unsigned ahi[4] = {ua.x, ub.x, ua.y, ub.y};
            unsigned alo[4] = {ua.z, ub.z, ua.w, ub.w};
            mma_f16(acc[af][0], ahi, bc0.x, bc0.y);
            mma_f16(acc[af][0], alo, bc0.x, bc0.y);
            mma_f16(acc[af][1], ahi, bc1.x, bc1.y);
            mma_f16(acc[af][1], alo, bc1.x, bc1.y);
        }

        bc0 = nb0; bc1 = nb1;
        nb0 = fb0; nb1 = fb1;
        pa1 = pa2;
        unsigned* tmp = Acur; Acur = Anxt; Anxt = Afree; Afree = tmp;
        __syncthreads();
    }

    #pragma unroll
    for (int af = 0; af < 2; af++) {
        int ra = r0 + af*16 + g;
        #pragma unroll
        for (int nt = 0; nt < 2; nt++) {
            int n0 = (ntg0 + wid*2 + nt)*8 + 2*t;
            float b0v = bias[n0], b1v = bias[n0 + 1];
            *(float2*)(outm + (size_t)ra*DD + n0) =
                make_float2(tanhf(acc[af][nt][0]*WSCALE_INV + b0v),
                            tanhf(acc[af][nt][1]*WSCALE_INV + b1v));
            *(float2*)(outm + (size_t)(ra+8)*DD + n0) =
                make_float2(tanhf(acc[af][nt][2]*WSCALE_INV + b0v),
                            tanhf(acc[af][nt][3]*WSCALE_INV + b1v));
        }
    }
}

// ============================================================================
// K6: init output with bias
// ============================================================================
__global__ void k_init_out(const float* __restrict__ b_bil, float* __restrict__ out) {
    int i = blockIdx.x*256 + threadIdx.x;
    if (i < RR*NOUT) out[i] = b_bil[i % NOUT];
}

// ============================================================================
// K7: bilinear via fp16 single-term A mma (unchanged).
// grid (48, 16) = 768 CTAs, 128 thr, 64-row r-tiles.
// ============================================================================
#define TS_OFF  0
#define HS_OFF  16896                       // 64*66*4
#define WB_OFF  (HS_OFF + 64*17*4)          // 21248
#define CHUNK_BYTES 3328                    // 13 nt * 32 lanes * 8B
#define BIL_SMEM (WB_OFF + 2*CHUNK_BYTES)   // 27904

__global__ void __launch_bounds__(128) k_bil_mma(float* __restrict__ out) {
    extern __shared__ __align__(16) char smem[];
    float* tsS = (float*)(smem + TS_OFF);   // [64 r][66]
    float* hsS = (float*)(smem + HS_OFF);   // [64 r][17]
    char*  Wbuf = smem + WB_OFF;

    const int kb = blockIdx.x >> 2;
    const int qt = blockIdx.x & 3;
    const int r0 = blockIdx.y * 64;
    const int tid  = threadIdx.x;
    const int wid  = tid >> 5;
    const int lane = tid & 31;
    const int g = lane >> 2, t = lane & 3;

    for (int idx = tid; idx < 64*64; idx += 128) {
        int rr = idx >> 6, j = idx & 63;
        tsS[rr*66 + j] = g_ts2[(size_t)(r0 + rr)*DD + kb*64 + j];
    }
    for (int idx = tid; idx < 64*16; idx += 128) {
        int rr = idx >> 4, ii = idx & 15;
        hsS[rr*17 + ii] = g_hs2[(size_t)(r0 + rr)*DD + kb*64 + qt*16 + ii];
    }
    const size_t chunk0 = (size_t)(kb*256 + qt*64);
    {
        const char* src = (const char*)g_Wp + chunk0*CHUNK_BYTES;
        for (int e = tid; e < 416; e += 128)
            *(uint2*)(Wbuf + e*8) = *(const uint2*)(src + e*8);
    }
    __syncthreads();

    float acc[13][4];
    #pragma unroll
    for (int n = 0; n < 13; n++)
        #pragma unroll
        for (int c = 0; c < 4; c++) acc[n][c] = 0.0f;

    for (int cc = 0; cc < 64; cc++) {
        int s = cc & 1;
        uint2 pw0, pw1, pw2, pw3;
        if (cc + 1 < 64) {
            const char* src = (const char*)g_Wp + (chunk0 + cc + 1)*CHUNK_BYTES;
            pw0 = *(const uint2*)(src + (tid      )*8);
            pw1 = *(const uint2*)(src + (tid + 128)*8);
            pw2 = *(const uint2*)(src + (tid + 256)*8);
            if (tid < 32) pw3 = *(const uint2*)(src + (tid + 384)*8);
        }

        int i_loc = cc >> 2;
        int j0    = (cc & 3) * 16;
        unsigned a[4];
        {
            int ra = wid*16 + g, rb = ra + 8;
            float hA = hsS[ra*17 + i_loc];
            float hB = hsS[rb*17 + i_loc];
            float2 tA0 = *(const float2*)&tsS[ra*66 + j0 + 2*t];
            float2 tA1 = *(const float2*)&tsS[ra*66 + j0 + 2*t + 8];
            float2 tB0 = *(const float2*)&tsS[rb*66 + j0 + 2*t];
            float2 tB1 = *(const float2*)&tsS[rb*66 + j0 + 2*t + 8];
            a[0] = pack_f16x2(hA*tA0.y, hA*tA0.x);
            a[1] = pack_f16x2(hB*tB0.y, hB*tB0.x);
            a[2] = pack_f16x2(hA*tA1.y, hA*tA1.x);
            a[3] = pack_f16x2(hB*tB1.y, hB*tB1.x);
        }

        #pragma unroll
        for (int nt = 0; nt < 13; nt++) {
            uint2 w = *(const uint2*)(Wbuf + s*CHUNK_BYTES + (nt*32 + lane)*8);
            mma_f16(acc[nt], a, w.x, w.y);
        }

        __syncthreads();
        if (cc + 1 < 64) {
            char* dst = Wbuf + (s^1)*CHUNK_BYTES;
            *(uint2*)(dst + (tid      )*8) = pw0;
            *(uint2*)(dst + (tid + 128)*8) = pw1;
            *(uint2*)(dst + (tid + 256)*8) = pw2;
            if (tid < 32) *(uint2*)(dst + (tid + 384)*8) = pw3;
        }
        __syncthreads();
    }

    {
        int r1 = r0 + wid*16 + g;
        #pragma unroll
        for (int nt = 0; nt < 13; nt++) {
            int n0 = nt*8 + 2*t;
            const float* av = acc[nt];
            if (n0 < NOUT) {
                atomicAdd(&out[(size_t)r1*NOUT + n0],     av[0]*WSCALE_INV);
                atomicAdd(&out[(size_t)(r1+8)*NOUT + n0], av[2]*WSCALE_INV);
            }
            if (n0 + 1 < NOUT) {
                atomicAdd(&out[(size_t)r1*NOUT + n0 + 1],     av[1]*WSCALE_INV);
                atomicAdd(&out[(size_t)(r1+8)*NOUT + n0 + 1], av[3]*WSCALE_INV);
            }
        }
    }
}

// ============================================================================
// launch: single stream; order chosen so k_rs_mma is the 4th kernel
// (harness ncu captures the 4th launch) while respecting all deps.
// ============================================================================
extern "C" void kernel_launch(void* const* d_in, const int* in_sizes, int n_in,
                              void* d_out, int out_size) {
    const float* seq    = (const float*)d_in[0];
    const float* att    = (const float*)d_in[1];
    const int*   mpos   = (const int*  )d_in[2];
    const int*   hts    = (const int*  )d_in[3];
    const float* W_head = (const float*)d_in[4];
    const float* b_head = (const float*)d_in[5];
    const float* W_tail = (const float*)d_in[6];
    const float* b_tail = (const float*)d_in[7];
    const float* W_bil  = (const float*)d_in[8];
    const float* b_bil  = (const float*)d_in[9];
    float* out = (float*)d_out;

    static int inited = 0;
    if (!inited) {
        cudaFuncSetAttribute(k_bil_mma, cudaFuncAttributeMaxDynamicSharedMemorySize, BIL_SMEM);
        inited = 1;
    }

    k_ent_att<<<NN*EE*HH, 256>>>(att, mpos);                    // 1
    k_ht_att<<<NN*PP, 256>>>(hts);                              // 2
    k_seqf<<<dim3(64, 4), 256>>>(seq);                          // 3
    k_rs_mma<<<dim3(12, 32), 128>>>();                          // 4  <- profiled
    k_wht<<<dim3(96, 2), 256>>>(W_head, W_tail);                // 5
    k_ent_emb<<<dim3(NN*EE, 2), 256>>>(seq, mpos);              // 6
    k_ht_mma<<<dim3(12, 32, 2), 128>>>(b_head, b_tail, hts);    // 7
    k_wt<<<3072, 128>>>(W_bil);                                 // 8
    k_init_out<<<(RR*NOUT + 255)/256, 256>>>(b_bil, out);       // 9
    k_bil_mma<<<dim3(KBL*4, RR/64), 128, BIL_SMEM>>>(out);      // 10
}

// round 13
// speedup vs baseline: 1.1149x; 1.1149x over previous
#include <cuda_runtime.h>
#include <math.h>

// ---------------- fixed problem shapes ----------------
#define NN   4
#define CC   1024
#define DD   768
#define HH   12
#define EE   32
#define MM   4
#define PP   256
#define RR   (NN*PP)     // 1024
#define KBL  12
#define NOUT 97

#define WSCALE     1024.0f
#define WSCALE_INV (1.0f/1024.0f)

// ---------------- scratch ----------------
__device__ float g_ent_emb[NN*EE*DD];
__device__ float g_ent_att[NN*EE*HH*CC];
__device__ float g_ht_att [NN*PP*CC];
__device__ float g_rs     [RR*DD];
__device__ float g_hs2    [RR*DD];
__device__ float g_ts2    [RR*DD];

// W_bil fragments (fp16, x1024): 3072 chunks x 13 nt x 32 lanes x uint2
__device__ __align__(16) unsigned char g_Wp[3072UL*13*32*8];
// W_head/W_tail fragments (fp16, x1024): [2][96 kc][96 nt][32] uint2
__device__ __align__(16) unsigned char g_Whtp[2UL*96*96*32*8];
// seq fragments (fp16, unscaled): [4][64 kc][96 nt][32] uint2
__device__ __align__(16) unsigned char g_seqf[4UL*64*96*32*8];

// ---------------- fp16 helpers ----------------
__device__ __forceinline__ unsigned pack_f16x2(float hi_f, float lo_f) {
    unsigned r;
    asm("cvt.rn.f16x2.f32 %0, %1, %2;" : "=r"(r) : "f"(hi_f), "f"(lo_f));
    return r;
}
// split (p0 lower, p1 upper) into f16x2 hi + f16x2 lo residual (~22-bit total)
__device__ __forceinline__ void split2h(float p0, float p1, unsigned& hi, unsigned& lo) {
    hi = pack_f16x2(p1, p0);
    float f0, f1;
    asm("{\n\t.reg .b16 h0, h1;\n\t"
        "mov.b32 {h0, h1}, %2;\n\t"
        "cvt.f32.f16 %0, h0;\n\t"
        "cvt.f32.f16 %1, h1;\n\t}"
        : "=f"(f0), "=f"(f1) : "r"(hi));
    lo = pack_f16x2(p1 - f1, p0 - f0);
}
// warp mma: D += A(f16) * B(f16), m16n8k16, row.col, fp32 accum
__device__ __forceinline__ void mma_f16(float* d, const unsigned* a,
                                        unsigned b0, unsigned b1) {
    asm volatile(
        "mma.sync.aligned.m16n8k16.row.col.f32.f16.f16.f32 "
        "{%0,%1,%2,%3}, {%4,%5,%6,%7}, {%8,%9}, {%0,%1,%2,%3};"
        : "+f"(d[0]), "+f"(d[1]), "+f"(d[2]), "+f"(d[3])
        : "r"(a[0]), "r"(a[1]), "r"(a[2]), "r"(a[3]), "r"(b0), "r"(b1));
}

// stage one float4 (pairs p0=2*quad, p0+1) into packed fragment row.
// slot(q) = q<4 ? 4q : 4(q-4)+1 ; hi at slot, lo at slot+2.
__device__ __forceinline__ void stage_pairs(unsigned* dst_row, int quad, float4 v) {
    unsigned hi0, lo0, hi1, lo1;
    split2h(v.x, v.y, hi0, lo0);
    split2h(v.z, v.w, hi1, lo1);
    int p0 = quad*2, p1 = p0 + 1;
    int s0 = (p0 < 4) ? 4*p0 : 4*(p0 - 4) + 1;
    int s1 = (p1 < 4) ? 4*p1 : 4*(p1 - 4) + 1;
    dst_row[s0] = hi0; dst_row[s0 + 2] = lo0;
    dst_row[s1] = hi1; dst_row[s1 + 2] = lo1;
}

// ============================================================================
// P0: pack W_bil (x1024, fp16) into B-fragment layout. grid 3072, 128 thr
// ============================================================================
__global__ void k_wt(const float* __restrict__ Wb) {
    __shared__ float Wsm[16*104];
    int chunk = blockIdx.x;
    int tid = threadIdx.x;
    int row0 = chunk * 16;

    for (int idx = tid; idx < 16*104; idx += 128) {
        int r = idx / 104, n = idx - r*104;
        Wsm[idx] = (n < NOUT) ? Wb[(size_t)(row0 + r)*NOUT + n] * WSCALE : 0.0f;
    }
    __syncthreads();

    for (int e = tid; e < 13*32; e += 128) {
        int nt = e >> 5, lane = e & 31;
        int g = lane >> 2, t = lane & 3;
        int n = nt*8 + g, k0 = 2*t;
        unsigned b0 = pack_f16x2(Wsm[(k0 + 1)*104 + n], Wsm[(k0    )*104 + n]);
        unsigned b1 = pack_f16x2(Wsm[(k0 + 9)*104 + n], Wsm[(k0 + 8)*104 + n]);
        *(uint2*)(g_Wp + ((size_t)(chunk*13 + nt)*32 + lane)*8) = make_uint2(b0, b1);
    }
}

// ============================================================================
// P1: pack W_head / W_tail (x1024, fp16). grid (96, 2), 256 thr
// ============================================================================
__global__ void k_wht(const float* __restrict__ Wh, const float* __restrict__ Wt) {
    __shared__ float S[16*768];
    int kc = blockIdx.x;
    int w  = blockIdx.y;
    const float* W = w ? Wt : Wh;
    int tid = threadIdx.x;

    for (int idx = tid; idx < 16*768; idx += 256)
        S[idx] = W[(size_t)kc*16*768 + idx] * WSCALE;
    __syncthreads();

    for (int e = tid; e < 96*32; e += 256) {
        int nt = e >> 5, lane = e & 31;
        int g = lane >> 2, t = lane & 3;
        int n = nt*8 + g, k0 = 2*t;
        unsigned b0 = pack_f16x2(S[(k0 + 1)*768 + n], S[(k0    )*768 + n]);
        unsigned b1 = pack_f16x2(S[(k0 + 9)*768 + n], S[(k0 + 8)*768 + n]);
        *(uint2*)(g_Whtp + ((((size_t)w*96 + kc)*96 + nt)*32 + lane)*8) = make_uint2(b0, b1);
    }
}

// ============================================================================
// P2: pack seq (fp16, unscaled). grid (64, 4), 256 thr
// ============================================================================
__global__ void k_seqf(const float* __restrict__ seq) {
    __shared__ float S[16*768];
    int kc = blockIdx.x;
    int b  = blockIdx.y;
    int tid = threadIdx.x;

    for (int idx = tid; idx < 16*768; idx += 256)
        S[idx] = seq[((size_t)b*CC + kc*16)*768 + idx];
    __syncthreads();

    for (int e = tid; e < 96*32; e += 256) {
        int nt = e >> 5, lane = e & 31;
        int g = lane >> 2, t = lane & 3;
        int n = nt*8 + g, k0 = 2*t;
        unsigned b0 = pack_f16x2(S[(k0 + 1)*768 + n], S[(k0    )*768 + n]);
        unsigned b1 = pack_f16x2(S[(k0 + 9)*768 + n], S[(k0 + 8)*768 + n]);
        *(uint2*)(g_seqf + ((((size_t)b*64 + kc)*96 + nt)*32 + lane)*8) = make_uint2(b0, b1);
    }
}

// ============================================================================
// K1: entity embeddings = logsumexp over M mentions. grid (128, 2)
// ============================================================================
__global__ void k_ent_emb(const float* __restrict__ seq,
                          const int*   __restrict__ mpos) {
    int be = blockIdx.x;
    int half = blockIdx.y;
    int b  = be / EE;
    const int* mp = mpos + be*MM;
    int p0 = mp[0], p1 = mp[1], p2 = mp[2], p3 = mp[3];
    const float* sb = seq + (long)b*CC*DD;
    int d0 = half*(DD/2), d1 = d0 + DD/2;
    for (int dd = d0 + threadIdx.x; dd < d1; dd += blockDim.x) {
        float v0 = sb[p0*DD+dd], v1 = sb[p1*DD+dd];
        float v2 = sb[p2*DD+dd], v3 = sb[p3*DD+dd];
        float mx = fmaxf(fmaxf(v0, v1), fmaxf(v2, v3));
        float s  = expf(v0-mx) + expf(v1-mx) + expf(v2-mx) + expf(v3-mx);
        g_ent_emb[be*DD + dd] = mx + logf(s);
    }
}

// ============================================================================
// K2: entity attention = mean over M mention attention rows
// ============================================================================
__global__ void k_ent_att(const float* __restrict__ att,
                          const int*   __restrict__ mpos) {
    int id = blockIdx.x;
    int hd = id % HH;
    int be = id / HH;
    int b  = be / EE;
    const int* mp = mpos + be*MM;
    const float* ab = att + (long)(b*HH + hd)*CC*CC;
    float* ob = g_ent_att + (long)id*CC;
    int q0 = mp[0]*CC, q1 = mp[1]*CC, q2 = mp[2]*CC, q3 = mp[3]*CC;
    for (int c = threadIdx.x; c < CC; c += blockDim.x) {
        float s = ab[q0+c] + ab[q1+c] + ab[q2+c] + ab[q3+c];
        ob[c] = s * 0.25f;
    }
}

// ============================================================================
// K3: ht_att = mean_h(h_att * t_att), row-normalized
// ============================================================================
__global__ void k_ht_att(const int* __restrict__ hts) {
    int bp = blockIdx.x;
    int b  = bp / PP;
    int eh = hts[bp*2 + 0];
    int et = hts[bp*2 + 1];
    const float* ah = g_ent_att + (long)(b*EE + eh)*HH*CC;
    const float* at = g_ent_att + (long)(b*EE + et)*HH*CC;

    float v[4];
    float lsum = 0.f;
    #pragma unroll
    for (int q = 0; q < 4; q++) {
        int c = q*256 + threadIdx.x;
        float s = 0.f;
        #pragma unroll
        for (int hd = 0; hd < HH; hd++)
            s += ah[hd*CC + c] * at[hd*CC + c];
        s *= (1.0f / HH);
        v[q] = s;
        lsum += s;
    }
    __shared__ float red[256];
    red[threadIdx.x] = lsum;
    __syncthreads();
    for (int st = 128; st > 0; st >>= 1) {
        if (threadIdx.x < st) red[threadIdx.x] += red[threadIdx.x + st];
        __syncthreads();
    }
    float inv = 1.0f / (red[0] + 1e-30f);
    #pragma unroll
    for (int q = 0; q < 4; q++) {
        int c = q*256 + threadIdx.x;
        g_ht_att[(long)bp*CC + c] = v[q] * inv;
    }
}

// ============================================================================
// K4: rs = ht_att @ seq, fp16 2-term mma, K-SPLIT x2 inside CTA.
// grid (12, 32), 256 thr: warps 0-3 K[0:512), warps 4-7 K[512:1024).
// Epilogue: smem exchange + add.
// ============================================================================
#define APITCH 20
__global__ void __launch_bounds__(256) k_rs_mma() {
    __shared__ __align__(16) unsigned As[2][2][32*APITCH];
    __shared__ __align__(16) float Xch[128*16];

    int ntg0 = blockIdx.x * 8;
    int r0   = blockIdx.y * 32;
    int b    = r0 >> 8;
    int tid = threadIdx.x;
    int kh  = tid >> 7;            // K-half
    int st  = tid & 127;
    int wid = st >> 5, lane = st & 31;
    int g = lane >> 2, t = lane & 3;
    int arow = st >> 2, quad = st & 3;

    const float* Arow = g_ht_att + (size_t)(r0 + arow)*CC + kh*512 + quad*4;
    const size_t KSTR = (size_t)96*256;
    const char* Bp0 = (const char*)g_seqf + (((size_t)b*64*96) + ntg0 + wid*2    )*256 + lane*8 + (size_t)(kh*32)*KSTR;
    const char* Bp1 = (const char*)g_seqf + (((size_t)b*64*96) + ntg0 + wid*2 + 1)*256 + lane*8 + (size_t)(kh*32)*KSTR;

    unsigned (*A)[32*APITCH] = As[kh];

    float4 pa = *(const float4*)(Arow);
    pa.x *= WSCALE; pa.y *= WSCALE; pa.z *= WSCALE; pa.w *= WSCALE;
    uint2 bc0 = *(const uint2*)(Bp0);
    uint2 bc1 = *(const uint2*)(Bp1);
    stage_pairs(&A[0][arow*APITCH], quad, pa);
    __syncthreads();

    float acc[2][2][4];
    #pragma unroll
    for (int a = 0; a < 2; a++)
        #pragma unroll
        for (int n = 0; n < 2; n++)
            #pragma unroll
            for (int c = 0; c < 4; c++) acc[a][n][c] = 0.0f;

    const int NKH = 32;
    uint2 pb0, pb1;
    for (int ks = 0; ks < NKH; ks++) {
        int s = ks & 1;
        if (ks + 1 < NKH) {
            pa = *(const float4*)(Arow + (ks + 1)*16);
            pa.x *= WSCALE; pa.y *= WSCALE; pa.z *= WSCALE; pa.w *= WSCALE;
            pb0 = *(const uint2*)(Bp0 + (size_t)(ks + 1)*KSTR);
            pb1 = *(const uint2*)(Bp1 + (size_t)(ks + 1)*KSTR);
        }

        #pragma unroll
        for (int af = 0; af < 2; af++) {
            int ra = af*16 + g, rb = ra + 8;
            uint4 ua = *(const uint4*)&A[s][ra*APITCH + 4*t];
            uint4 ub = *(const uint4*)&A[s][rb*APITCH + 4*t];
            unsigned ahi[4] = {ua.x, ub.x, ua.y, ub.y};
            unsigned alo[4] = {ua.z, ub.z, ua.w, ub.w};
            mma_f16(acc[af][0], ahi, bc0.x, bc0.y);
            mma_f16(acc[af][0], alo, bc0.x, bc0.y);
            mma_f16(acc[af][1], ahi, bc1.x, bc1.y);
            mma_f16(acc[af][1], alo, bc1.x, bc1.y);
        }

        if (ks + 1 < NKH) {
            stage_pairs(&A[s^1][arow*APITCH], quad, pa);
            bc0 = pb0; bc1 = pb1;
        }
        __syncthreads();
    }

    // combine halves
    if (kh == 1) {
        #pragma unroll
        for (int af = 0; af < 2; af++)
            #pragma unroll
            for (int nt = 0; nt < 2; nt++)
                *(float4*)&Xch[st*16 + af*8 + nt*4] =
                    make_float4(acc[af][nt][0], acc[af][nt][1], acc[af][nt][2], acc[af][nt][3]);
    }
    __syncthreads();
    if (kh == 0) {
        #pragma unroll
        for (int af = 0; af < 2; af++) {
            int ra = r0 + af*16 + g;
            #pragma unroll
            for (int nt = 0; nt < 2; nt++) {
                float4 o = *(const float4*)&Xch[st*16 + af*8 + nt*4];
                int n0 = (ntg0 + wid*2 + nt)*8 + 2*t;
                *(float2*)(g_rs + (size_t)ra*DD + n0) =
                    make_float2((acc[af][nt][0] + o.x)*WSCALE_INV, (acc[af][nt][1] + o.y)*WSCALE_INV);
                *(float2*)(g_rs + (size_t)(ra+8)*DD + n0) =
                    make_float2((acc[af][nt][2] + o.z)*WSCALE_INV, (acc[af][nt][3] + o.w)*WSCALE_INV);
            }
        }
    }
}

// ============================================================================
// K5: hs2/ts2 = tanh(concat(ent_emb[ent], rs) @ W + b), K-SPLIT x2.
// grid (12, 32, 2), 256 thr: warps 0-3 = ent_emb half, warps 4-7 = rs half.
// ============================================================================
__global__ void __launch_bounds__(256) k_ht_mma(const float* __restrict__ bh,
                                                const float* __restrict__ bt,
                                                const int* __restrict__ hts) {
    __shared__ __align__(16) unsigned As[2][2][32*APITCH];
    __shared__ __align__(16) float Xch[128*16];
    __shared__ int eOff[32];

    int ntg0 = blockIdx.x * 8;
    int r0   = blockIdx.y * 32;
    int col  = blockIdx.z;
    const float* bias = col ? bt : bh;
    float* outm = col ? g_ts2 : g_hs2;

    int tid = threadIdx.x;
    int kh  = tid >> 7;
    int st  = tid & 127;
    int wid = st >> 5, lane = st & 31;
    int g = lane >> 2, t = lane & 3;
    int arow = st >> 2, quad = st & 3;

    if (tid < 32) {
        int r = r0 + tid;
        eOff[tid] = ((r >> 8)*EE + hts[r*2 + col])*DD;
    }
    __syncthreads();

    const float* srcRow = (kh == 0)
        ? (g_ent_emb + eOff[arow] + quad*4)
        : (g_rs + (size_t)(r0 + arow)*DD + quad*4);

    const size_t KSTR = (size_t)96*256;
    const char* Bp0 = (const char*)g_Whtp + (((size_t)col*96*96) + ntg0 + wid*2    )*256 + lane*8 + (size_t)(kh*48)*KSTR;
    const char* Bp1 = (const char*)g_Whtp + (((size_t)col*96*96) + ntg0 + wid*2 + 1)*256 + lane*8 + (size_t)(kh*48)*KSTR;

    unsigned (*A)[32*APITCH] = As[kh];

    float4 pa = *(const float4*)(srcRow);
    uint2 bc0 = *(const uint2*)(Bp0);
    uint2 bc1 = *(const uint2*)(Bp1);
    stage_pairs(&A[0][arow*APITCH], quad, pa);
    __syncthreads();

    float acc[2][2][4];
    #pragma unroll
    for (int a = 0; a < 2; a++)
        #pragma unroll
        for (int n = 0; n < 2; n++)
            #pragma unroll
            for (int c = 0; c < 4; c++) acc[a][n][c] = 0.0f;

    const int NKH = 48;
    uint2 pb0, pb1;
    for (int ks = 0; ks < NKH; ks++) {
        int s = ks & 1;
        if (ks + 1 < NKH) {
            pa = *(const float4*)(srcRow + (ks + 1)*16);
            pb0 = *(const uint2*)(Bp0 + (size_t)(ks + 1)*KSTR);
            pb1 = *(const uint2*)(Bp1 + (size_t)(ks + 1)*KSTR);
        }

        #pragma unroll
        for (int af = 0; af < 2; af++) {
            int ra = af*16 + g, rb = ra + 8;
            uint4 ua = *(const uint4*)&A[s][ra*APITCH + 4*t];
            uint4 ub = *(const uint4*)&A[s][rb*APITCH + 4*t];
            unsigned ahi[4] = {ua.x, ub.x, ua.y, ub.y};
            unsigned alo[4] = {ua.z, ub.z, ua.w, ub.w};
            mma_f16(acc[af][0], ahi, bc0.x, bc0.y);
            mma_f16(acc[af][0], alo, bc0.x, bc0.y);
            mma_f16(acc[af][1], ahi, bc1.x, bc1.y);
            mma_f16(acc[af][1], alo, bc1.x, bc1.y);
        }

        if (ks + 1 < NKH) {
            stage_pairs(&A[s^1][arow*APITCH], quad, pa);
            bc0 = pb0; bc1 = pb1;
        }
        __syncthreads();
    }

    if (kh == 1) {
        #pragma unroll
        for (int af = 0; af < 2; af++)
            #pragma unroll
            for (int nt = 0; nt < 2; nt++)
                *(float4*)&Xch[st*16 + af*8 + nt*4] =
                    make_float4(acc[af][nt][0], acc[af][nt][1], acc[af][nt][2], acc[af][nt][3]);
    }
    __syncthreads();
    if (kh == 0) {
        #pragma unroll
        for (int af = 0; af < 2; af++) {
            int ra = r0 + af*16 + g;
            #pragma unroll
            for (int nt = 0; nt < 2; nt++) {
                float4 o = *(const float4*)&Xch[st*16 + af*8 + nt*4];
                int n0 = (ntg0 + wid*2 + nt)*8 + 2*t;
                float b0v = bias[n0], b1v = bias[n0 + 1];
                *(float2*)(outm + (size_t)ra*DD + n0) =
                    make_float2(tanhf((acc[af][nt][0] + o.x)*WSCALE_INV + b0v),
                                tanhf((acc[af][nt][1] + o.y)*WSCALE_INV + b1v));
                *(float2*)(outm + (size_t)(ra+8)*DD + n0) =
                    make_float2(tanhf((acc[af][nt][2] + o.z)*WSCALE_INV + b0v),
                                tanhf((acc[af][nt][3] + o.w)*WSCALE_INV + b1v));
            }
        }
    }
}

// ============================================================================
// K6: init output with bias
// ============================================================================
__global__ void k_init_out(const float* __restrict__ b_bil, float* __restrict__ out) {
    int i = blockIdx.x*256 + threadIdx.x;
    if (i < RR*NOUT) out[i] = b_bil[i % NOUT];
}

// ============================================================================
// K7: bilinear via fp16 single-term A mma (unchanged).
// grid (48, 16) = 768 CTAs, 128 thr, 64-row r-tiles.
// ============================================================================
#define TS_OFF  0
#define HS_OFF  16896                       // 64*66*4
#define WB_OFF  (HS_OFF + 64*17*4)          // 21248
#define CHUNK_BYTES 3328                    // 13 nt * 32 lanes * 8B
#define BIL_SMEM (WB_OFF + 2*CHUNK_BYTES)   // 27904

__global__ void __launch_bounds__(128) k_bil_mma(float* __restrict__ out) {
    extern __shared__ __align__(16) char smem[];
    float* tsS = (float*)(smem + TS_OFF);   // [64 r][66]
    float* hsS = (float*)(smem + HS_OFF);   // [64 r][17]
    char*  Wbuf = smem + WB_OFF;

    const int kb = blockIdx.x >> 2;
    const int qt = blockIdx.x & 3;
    const int r0 = blockIdx.y * 64;
    const int tid  = threadIdx.x;
    const int wid  = tid >> 5;
    const int lane = tid & 31;
    const int g = lane >> 2, t = lane & 3;

    for (int idx = tid; idx < 64*64; idx += 128) {
        int rr = idx >> 6, j = idx & 63;
        tsS[rr*66 + j] = g_ts2[(size_t)(r0 + rr)*DD + kb*64 + j];
    }
    for (int idx = tid; idx < 64*16; idx += 128) {
        int rr = idx >> 4, ii = idx & 15;
        hsS[rr*17 + ii] = g_hs2[(size_t)(r0 + rr)*DD + kb*64 + qt*16 + ii];
    }
    const size_t chunk0 = (size_t)(kb*256 + qt*64);
    {
        const char* src = (const char*)g_Wp + chunk0*CHUNK_BYTES;
        for (int e = tid; e < 416; e += 128)
            *(uint2*)(Wbuf + e*8) = *(const uint2*)(src + e*8);
    }
    __syncthreads();

    float acc[13][4];
    #pragma unroll
    for (int n = 0; n < 13; n++)
        #pragma unroll
        for (int c = 0; c < 4; c++) acc[n][c] = 0.0f;

    for (int cc = 0; cc < 64; cc++) {
        int s = cc & 1;
        uint2 pw0, pw1, pw2, pw3;
        if (cc + 1 < 64) {
            const char* src = (const char*)g_Wp + (chunk0 + cc + 1)*CHUNK_BYTES;
            pw0 = *(const uint2*)(src + (tid      )*8);
            pw1 = *(const uint2*)(src + (tid + 128)*8);
            pw2 = *(const uint2*)(src + (tid + 256)*8);
            if (tid < 32) pw3 = *(const uint2*)(src + (tid + 384)*8);
        }

        int i_loc = cc >> 2;
        int j0    = (cc & 3) * 16;
        unsigned a[4];
        {
            int ra = wid*16 + g, rb = ra + 8;
            float hA = hsS[ra*17 + i_loc];
            float hB = hsS[rb*17 + i_loc];
            float2 tA0 = *(const float2*)&tsS[ra*66 + j0 + 2*t];
            float2 tA1 = *(const float2*)&tsS[ra*66 + j0 + 2*t + 8];
            float2 tB0 = *(const float2*)&tsS[rb*66 + j0 + 2*t];
            float2 tB1 = *(const float2*)&tsS[rb*66 + j0 + 2*t + 8];
            a[0] = pack_f16x2(hA*tA0.y, hA*tA0.x);
            a[1] = pack_f16x2(hB*tB0.y, hB*tB0.x);
            a[2] = pack_f16x2(hA*tA1.y, hA*tA1.x);
            a[3] = pack_f16x2(hB*tB1.y, hB*tB1.x);
        }

        #pragma unroll
        for (int nt = 0; nt < 13; nt++) {
            uint2 w = *(const uint2*)(Wbuf + s*CHUNK_BYTES + (nt*32 + lane)*8);
            mma_f16(acc[nt], a, w.x, w.y);
        }

        __syncthreads();
        if (cc + 1 < 64) {
            char* dst = Wbuf + (s^1)*CHUNK_BYTES;
            *(uint2*)(dst + (tid      )*8) = pw0;
            *(uint2*)(dst + (tid + 128)*8) = pw1;
            *(uint2*)(dst + (tid + 256)*8) = pw2;
            if (tid < 32) *(uint2*)(dst + (tid + 384)*8) = pw3;
        }
        __syncthreads();
    }

    {
        int r1 = r0 + wid*16 + g;
        #pragma unroll
        for (int nt = 0; nt < 13; nt++) {
            int n0 = nt*8 + 2*t;
            const float* av = acc[nt];
            if (n0 < NOUT) {
                atomicAdd(&out[(size_t)r1*NOUT + n0],     av[0]*WSCALE_INV);
                atomicAdd(&out[(size_t)(r1+8)*NOUT + n0], av[2]*WSCALE_INV);
            }
            if (n0 + 1 < NOUT) {
                atomicAdd(&out[(size_t)r1*NOUT + n0 + 1],     av[1]*WSCALE_INV);
                atomicAdd(&out[(size_t)(r1+8)*NOUT + n0 + 1], av[3]*WSCALE_INV);
            }
        }
    }
}

// ============================================================================
// launch: multi-stream DAG; k_rs_mma kept as 4th launch for profiling.
// ============================================================================
extern "C" void kernel_launch(void* const* d_in, const int* in_sizes, int n_in,
                              void* d_out, int out_size) {
    const float* seq    = (const float*)d_in[0];
    const float* att    = (const float*)d_in[1];
    const int*   mpos   = (const int*  )d_in[2];
    const int*   hts    = (const int*  )d_in[3];
    const float* W_head = (const float*)d_in[4];
    const float* b_head = (const float*)d_in[5];
    const float* W_tail = (const float*)d_in[6];
    const float* b_tail = (const float*)d_in[7];
    const float* W_bil  = (const float*)d_in[8];
    const float* b_bil  = (const float*)d_in[9];
    float* out = (float*)d_out;

    static cudaStream_t s1, s2, s3;
    static cudaEvent_t evRoot, evA, evB, evC, evD, evF;
    static int inited = 0;
    if (!inited) {
        cudaStreamCreateWithFlags(&s1, cudaStreamNonBlocking);
        cudaStreamCreateWithFlags(&s2, cudaStreamNonBlocking);
        cudaStreamCreateWithFlags(&s3, cudaStreamNonBlocking);
        cudaEventCreateWithFlags(&evRoot, cudaEventDisableTiming);
        cudaEventCreateWithFlags(&evA, cudaEventDisableTiming);
        cudaEventCreateWithFlags(&evB, cudaEventDisableTiming);
        cudaEventCreateWithFlags(&evC, cudaEventDisableTiming);
        cudaEventCreateWithFlags(&evD, cudaEventDisableTiming);
        cudaEventCreateWithFlags(&evF, cudaEventDisableTiming);
        cudaFuncSetAttribute(k_bil_mma, cudaFuncAttributeMaxDynamicSharedMemorySize, BIL_SMEM);
        inited = 1;
    }

    cudaEventRecord(evRoot, 0);
    cudaStreamWaitEvent(s1, evRoot, 0);
    cudaStreamWaitEvent(s2, evRoot, 0);
    cudaStreamWaitEvent(s3, evRoot, 0);

    k_ent_att<<<NN*EE*HH, 256>>>(att, mpos);                    // 1 (main)
    k_ht_att<<<NN*PP, 256>>>(hts);                              // 2 (main)
    k_seqf<<<dim3(64, 4), 256, 0, s2>>>(seq);                   // 3 (s2)
    cudaEventRecord(evC, s2);
    cudaStreamWaitEvent(0, evC, 0);
    k_rs_mma<<<dim3(12, 32), 256>>>();                          // 4 (main) <- profiled
    k_wht<<<dim3(96, 2), 256, 0, s2>>>(W_head, W_tail);         // 5 (s2)
    cudaEventRecord(evB, s2);
    k_ent_emb<<<dim3(NN*EE, 2), 256, 0, s3>>>(seq, mpos);       // 6 (s3)
    cudaEventRecord(evD, s3);
    cudaStreamWaitEvent(0, evB, 0);
    cudaStreamWaitEvent(0, evD, 0);
    k_ht_mma<<<dim3(12, 32, 2), 256>>>(b_head, b_tail, hts);    // 7 (main)
    k_wt<<<3072, 128, 0, s1>>>(W_bil);                          // 8 (s1, runs early)
    cudaEventRecord(evA, s1);
    k_init_out<<<(RR*NOUT + 255)/256, 256, 0, s3>>>(b_bil, out);// 9 (s3)
    cudaEventRecord(evF, s3);
    cudaStreamWaitEvent(0, evA, 0);
    cudaStreamWaitEvent(0, evF, 0);
    k_bil_mma<<<dim3(KBL*4, RR/64), 128, BIL_SMEM>>>(out);      // 10 (main)
}